// round 16
// baseline (speedup 1.0000x reference)
#include <cuda_runtime.h>
#include <cuda_bf16.h>
#include <cstdint>
#include <cstring>

#define HIDDEN 1024
#define BB 8
#define SS 1024
#define NH 16
#define HD 64
#define SCALE 0.125f
#define NELEM (BB * SS * HIDDEN)     // 8M

// ---------------------------------------------------------------------------
// Scratch (no cudaMalloc allowed).
// ---------------------------------------------------------------------------
// int8 2-limb quantized GEMM inputs + per-row scales
__device__ int8_t g_q0[NELEM],  g_q1[NELEM];
__device__ int8_t g_k0[NELEM],  g_k1[NELEM];
__device__ int8_t g_v0[NELEM],  g_v1[NELEM];
__device__ int8_t g_c0[NELEM],  g_c1[NELEM];
__device__ int8_t g_Wq0[HIDDEN*HIDDEN], g_Wq1[HIDDEN*HIDDEN];
__device__ int8_t g_Wk0[HIDDEN*HIDDEN], g_Wk1[HIDDEN*HIDDEN];
__device__ int8_t g_Wv0[HIDDEN*HIDDEN], g_Wv1[HIDDEN*HIDDEN];
__device__ int8_t g_Wo0[HIDDEN*HIDDEN], g_Wo1[HIDDEN*HIDDEN];
__device__ float g_sq[BB*SS], g_sk[BB*SS], g_sv[BB*SS], g_sc[BB*SS];
__device__ float g_sWq[HIDDEN], g_sWk[HIDDEN], g_sWv[HIDDEN], g_sWo[HIDDEN];
// flash inputs (bf16 split) and fp32 ctx output
__device__ __nv_bfloat16 g_Qsh[NELEM], g_Qsl[NELEM];   // [b,h,s,d]
__device__ __nv_bfloat16 g_Ksh[NELEM], g_Ksl[NELEM];   // [b,h,s,d]
__device__ __nv_bfloat16 g_Vth[NELEM], g_Vtl[NELEM];   // [b,h,d,s]
__device__ float g_CtxF[NELEM];                        // [b,s,1024]

__device__ __forceinline__ uint32_t b2u(__nv_bfloat162 h) {
    uint32_t u; memcpy(&u, &h, 4); return u;
}

__device__ __forceinline__ void mma16816(float* c, const uint32_t* a, const uint32_t* b) {
    asm volatile(
        "mma.sync.aligned.m16n8k16.row.col.f32.bf16.bf16.f32 "
        "{%0,%1,%2,%3}, {%4,%5,%6,%7}, {%8,%9}, {%0,%1,%2,%3};"
        : "+f"(c[0]), "+f"(c[1]), "+f"(c[2]), "+f"(c[3])
        : "r"(a[0]), "r"(a[1]), "r"(a[2]), "r"(a[3]), "r"(b[0]), "r"(b[1]));
}

__device__ __forceinline__ void mma_s8(int* c, const uint32_t* a, const uint32_t* b) {
    asm volatile(
        "mma.sync.aligned.m16n8k32.row.col.s32.s8.s8.s32 "
        "{%0,%1,%2,%3}, {%4,%5,%6,%7}, {%8,%9}, {%0,%1,%2,%3};"
        : "+r"(c[0]), "+r"(c[1]), "+r"(c[2]), "+r"(c[3])
        : "r"(a[0]), "r"(a[1]), "r"(a[2]), "r"(a[3]), "r"(b[0]), "r"(b[1]));
}

__device__ __forceinline__ uint32_t smem_u32(const void* p) {
    uint32_t a;
    asm("{ .reg .u64 t; cvta.to.shared.u64 t, %1; cvt.u32.u64 %0, t; }" : "=r"(a) : "l"(p));
    return a;
}

#define CP_ASYNC16(dst, src) \
    asm volatile("cp.async.cg.shared.global [%0], [%1], 16;" :: "r"(dst), "l"(src))
#define CP_COMMIT() asm volatile("cp.async.commit_group;" ::: "memory")
#define CP_WAIT(n)  asm volatile("cp.async.wait_group %0;" :: "n"(n) : "memory")

__device__ __forceinline__ void split_store2(float x, float y,
                                             __nv_bfloat16* H, __nv_bfloat16* L, size_t off) {
    __nv_bfloat162 hp = __floats2bfloat162_rn(x, y);
    float2 hf = __bfloat1622float2(hp);
    __nv_bfloat162 lp = __floats2bfloat162_rn(x - hf.x, y - hf.y);
    *(uint32_t*)(H + off) = b2u(hp);
    *(uint32_t*)(L + off) = b2u(lp);
}

__device__ __forceinline__ void split_store1(float x, __nv_bfloat16* H, __nv_bfloat16* L, size_t off) {
    __nv_bfloat16 h = __float2bfloat16(x);
    H[off] = h;
    L[off] = __float2bfloat16(x - __bfloat162float(h));
}

// ---------------------------------------------------------------------------
// Per-row int8 2-limb quantization: x = s*(a0*128 + a1), stored scale = max/127
// One block per row of 1024 floats.
// ---------------------------------------------------------------------------
__global__ __launch_bounds__(256)
void quant_kernel(const float* __restrict__ X, int8_t* __restrict__ X0,
                  int8_t* __restrict__ X1, float* __restrict__ Xs)
{
    __shared__ float smax[256];
    const int row = blockIdx.x, tid = threadIdx.x;
    float4 v = ((const float4*)(X + (size_t)row * HIDDEN))[tid];
    float mx = fmaxf(fmaxf(fabsf(v.x), fabsf(v.y)), fmaxf(fabsf(v.z), fabsf(v.w)));
    smax[tid] = mx;
    __syncthreads();
#pragma unroll
    for (int st = 128; st > 0; st >>= 1) {
        if (tid < st) smax[tid] = fmaxf(smax[tid], smax[tid + st]);
        __syncthreads();
    }
    float m = smax[0];
    float s16 = (m > 0.f) ? m / 16256.f : 1.f;
    if (tid == 0) Xs[row] = s16 * 128.f;   // pre-multiplied: sA*sB absorbs 128*128
    float inv = 1.f / s16;
    float xv[4] = {v.x, v.y, v.z, v.w};
    char a0[4], a1[4];
#pragma unroll
    for (int j = 0; j < 4; j++) {
        int mi = __float2int_rn(xv[j] * inv);
        int h = __float2int_rn((float)mi * 0.0078125f);
        h = max(-127, min(127, h));
        a0[j] = (char)h;
        a1[j] = (char)(mi - (h << 7));
    }
    ((char4*)X0)[(size_t)row * 256 + tid] = make_char4(a0[0], a0[1], a0[2], a0[3]);
    ((char4*)X1)[(size_t)row * 256 + tid] = make_char4(a1[0], a1[1], a1[2], a1[3]);
}

// ---------------------------------------------------------------------------
// int8 2-limb GEMM: C[m,n] = sA[m]*sB[n]*(acc0 + acc1/128) + bias[n]
// 3 s8 MMAs per k32 (vs 6 bf16-equivalent) -> half the MMA instructions.
// 256 threads, 8 warps (2x4), warp tile 64x32, K-chunk 64, 2-stage cp.async.
// mode 0: split-bf16 out [b,h,s,d]; mode 1: fp32 row-major; mode 2: split Vt
// ---------------------------------------------------------------------------
#define Q_RS 80                        // 64B data + 16B pad per row
#define Q_BUF (128 * Q_RS)             // 10240
#define Q_STG (4 * Q_BUF)              // 40960 (A0, A1, B0, B1)
#define QGEMM_SMEM (2 * Q_STG)         // 81920

__global__ __launch_bounds__(256)
void gemm_s8_kernel(const int8_t* __restrict__ A0, const int8_t* __restrict__ A1,
                    const int8_t* __restrict__ B0, const int8_t* __restrict__ B1,
                    const float* __restrict__ sA, const float* __restrict__ sB,
                    const float* __restrict__ bias, float* __restrict__ outF,
                    __nv_bfloat16* __restrict__ Oh, __nv_bfloat16* __restrict__ Ol, int mode)
{
    extern __shared__ char dsm[];
    const uint32_t su = smem_u32(dsm);
    const int tid = threadIdx.x;
    const int wid = tid >> 5, lane = tid & 31;
    const int lr = lane >> 2, lc = lane & 3;
    const int n0 = blockIdx.x * 128, m0 = blockIdx.y * 128;
    const int wm = (wid >> 2) * 64;
    const int wn = (wid & 3) * 32;

    int acc0[4][4][4], acc1[4][4][4];
#pragma unroll
    for (int i = 0; i < 4; i++)
#pragma unroll
        for (int j = 0; j < 4; j++)
#pragma unroll
            for (int r = 0; r < 4; r++) { acc0[i][j][r] = 0; acc1[i][j][r] = 0; }

    // stage loader: 4 buffers x 128 rows x 64B; 8 cp.async per thread
#define Q_LOAD(s, kt) do { \
    uint32_t base = su + (s) * Q_STG; \
    int sg = tid & 3; \
    _Pragma("unroll") \
    for (int half = 0; half < 2; half++) { \
        int row = half * 64 + (tid >> 2); \
        uint32_t d = base + row * Q_RS + sg * 16; \
        size_t goA = (size_t)(m0 + row) * HIDDEN + (kt) * 64 + sg * 16; \
        size_t goB = (size_t)(n0 + row) * HIDDEN + (kt) * 64 + sg * 16; \
        CP_ASYNC16(d,             A0 + goA); \
        CP_ASYNC16(d + Q_BUF,     A1 + goA); \
        CP_ASYNC16(d + 2 * Q_BUF, B0 + goB); \
        CP_ASYNC16(d + 3 * Q_BUF, B1 + goB); \
    } \
} while (0)

    Q_LOAD(0, 0);
    CP_COMMIT();

    for (int kt = 0; kt < 16; kt++) {
        if (kt < 15) {
            Q_LOAD((kt + 1) & 1, kt + 1);
            CP_COMMIT();
            CP_WAIT(1);
        } else {
            CP_WAIT(0);
        }
        __syncthreads();

        char* s0 = dsm + (kt & 1) * Q_STG;          // A0
        char* s1 = s0 + Q_BUF;                       // A1
        char* s2 = s0 + 2 * Q_BUF;                   // B0
        char* s3 = s0 + 3 * Q_BUF;                   // B1

#pragma unroll
        for (int ks = 0; ks < 2; ks++) {
            const uint32_t kb = ks * 32;
            uint32_t B0f[4][2], B1f[4][2];
#pragma unroll
            for (int jn = 0; jn < 4; jn++) {
                uint32_t boff = (wn + jn * 8 + lr) * Q_RS + kb + lc * 4;
                B0f[jn][0] = *(const uint32_t*)(s2 + boff);
                B0f[jn][1] = *(const uint32_t*)(s2 + boff + 16);
                B1f[jn][0] = *(const uint32_t*)(s3 + boff);
                B1f[jn][1] = *(const uint32_t*)(s3 + boff + 16);
            }
            uint32_t A0f[4][4], A1f[4][4];
#pragma unroll
            for (int i = 0; i < 4; i++) {
                uint32_t aoff = (wm + i * 16 + lr) * Q_RS + kb + lc * 4;
                A0f[i][0] = *(const uint32_t*)(s0 + aoff);
                A0f[i][1] = *(const uint32_t*)(s0 + aoff + 8 * Q_RS);
                A0f[i][2] = *(const uint32_t*)(s0 + aoff + 16);
                A0f[i][3] = *(const uint32_t*)(s0 + aoff + 8 * Q_RS + 16);
                A1f[i][0] = *(const uint32_t*)(s1 + aoff);
                A1f[i][1] = *(const uint32_t*)(s1 + aoff + 8 * Q_RS);
                A1f[i][2] = *(const uint32_t*)(s1 + aoff + 16);
                A1f[i][3] = *(const uint32_t*)(s1 + aoff + 8 * Q_RS + 16);
            }
#pragma unroll
            for (int i = 0; i < 4; i++)
#pragma unroll
                for (int jn = 0; jn < 4; jn++)
                    mma_s8(acc0[i][jn], A0f[i], B0f[jn]);
#pragma unroll
            for (int i = 0; i < 4; i++)
#pragma unroll
                for (int jn = 0; jn < 4; jn++)
                    mma_s8(acc1[i][jn], A0f[i], B1f[jn]);
#pragma unroll
            for (int i = 0; i < 4; i++)
#pragma unroll
                for (int jn = 0; jn < 4; jn++)
                    mma_s8(acc1[i][jn], A1f[i], B0f[jn]);
        }
        __syncthreads();
    }

#pragma unroll
    for (int i = 0; i < 4; i++) {
#pragma unroll
        for (int jn = 0; jn < 4; jn++) {
            int row = m0 + wm + i * 16 + lr;
            int row8 = row + 8;
            int col = n0 + wn + jn * 8 + lc * 2;
            float fa0 = sA[row], fa1 = sA[row8];
            float fw0 = sB[col], fw1 = sB[col + 1];
            float x0 = ((float)acc0[i][jn][0] + (float)acc1[i][jn][0] * 0.0078125f) * (fa0 * fw0) + bias[col];
            float y0 = ((float)acc0[i][jn][1] + (float)acc1[i][jn][1] * 0.0078125f) * (fa0 * fw1) + bias[col + 1];
            float x1 = ((float)acc0[i][jn][2] + (float)acc1[i][jn][2] * 0.0078125f) * (fa1 * fw0) + bias[col];
            float y1 = ((float)acc0[i][jn][3] + (float)acc1[i][jn][3] * 0.0078125f) * (fa1 * fw1) + bias[col + 1];
            if (mode == 0) {
                int b0_ = row >> 10, s0_ = row & 1023;
                int b1_ = row8 >> 10, s1_ = row8 & 1023;
                int h = col >> 6, d = col & 63;
                split_store2(x0, y0, Oh, Ol, (((size_t)(b0_ * NH + h)) * SS + s0_) * HD + d);
                split_store2(x1, y1, Oh, Ol, (((size_t)(b1_ * NH + h)) * SS + s1_) * HD + d);
            } else if (mode == 1) {
                *(float2*)(outF + (size_t)row * HIDDEN + col) = make_float2(x0, y0);
                *(float2*)(outF + (size_t)row8 * HIDDEN + col) = make_float2(x1, y1);
            } else {
                int b0_ = row >> 10, s0_ = row & 1023;
                int s1_ = row8 & 1023;
                int h = col >> 6, d = col & 63;
                size_t base = (size_t)(b0_ * NH + h) * HD;
                split_store1(x0, Oh, Ol, (base + d) * SS + s0_);
                split_store1(y0, Oh, Ol, (base + d + 1) * SS + s0_);
                split_store1(x1, Oh, Ol, (base + d) * SS + s1_);
                split_store1(y1, Oh, Ol, (base + d + 1) * SS + s1_);
            }
        }
    }
}

// ---------------------------------------------------------------------------
// Tensor-core flash attention (bf16 3-pass, unchanged math); writes fp32 Ctx.
// ---------------------------------------------------------------------------
#define F_QH 0
#define F_QL 18432
#define F_K(s) (36864 + (s) * 36864)
#define F_V(s) (110592 + (s) * 34816)
#define F_ZS 180224
#define FLASH_SMEM (F_ZS + 1152 * 4)

__global__ __launch_bounds__(256)
void flash_tc_kernel(const __nv_bfloat16* __restrict__ Qhg, const __nv_bfloat16* __restrict__ Qlg,
                     const __nv_bfloat16* __restrict__ Khg, const __nv_bfloat16* __restrict__ Klg,
                     const __nv_bfloat16* __restrict__ Vthg, const __nv_bfloat16* __restrict__ Vtlg,
                     const float* __restrict__ attn_bias, const float* __restrict__ zoom,
                     float* __restrict__ CtxF)
{
    extern __shared__ char sm[];
    const uint32_t su = smem_u32(sm);
    float* zs = (float*)(sm + F_ZS);

    const int tid = threadIdx.x;
    const int wid = tid >> 5, lane = tid & 31;
    const int lr = lane >> 2, lc = lane & 3;
    const int wq = wid * 16;
    const int qt = blockIdx.x, h = blockIdx.y, b = blockIdx.z;
    const int qr0 = qt * 128;

    const __nv_bfloat16* gQh  = Qhg + (((size_t)(b * NH + h)) * SS + qr0) * HD;
    const __nv_bfloat16* gQl  = Qlg + (((size_t)(b * NH + h)) * SS + qr0) * HD;
    const __nv_bfloat16* gKh  = Khg + ((size_t)(b * NH + h)) * SS * HD;
    const __nv_bfloat16* gKl  = Klg + ((size_t)(b * NH + h)) * SS * HD;
    const __nv_bfloat16* gVth = Vthg + ((size_t)(b * NH + h)) * HD * SS;
    const __nv_bfloat16* gVtl = Vtlg + ((size_t)(b * NH + h)) * HD * SS;
    const float* gB = attn_bias + (size_t)b * SS * SS;

#define F_LOAD(s, t0) do { \
    _Pragma("unroll") \
    for (int li = 0; li < 4; li++) { \
        int idx = tid + li * 256; \
        int row = idx >> 3, seg = idx & 7; \
        uint32_t dk = su + F_K(s) + row * 144 + seg * 16; \
        CP_ASYNC16(dk,         gKh + (size_t)((t0) + row) * HD + seg * 8); \
        CP_ASYNC16(dk + 18432, gKl + (size_t)((t0) + row) * HD + seg * 8); \
    } \
    _Pragma("unroll") \
    for (int li = 0; li < 4; li++) { \
        int idx = tid + li * 256; \
        int d = idx >> 4, seg = idx & 15; \
        uint32_t dv = su + F_V(s) + d * 272 + seg * 16; \
        CP_ASYNC16(dv,         gVth + (size_t)d * SS + (t0) + seg * 8); \
        CP_ASYNC16(dv + 17408, gVtl + (size_t)d * SS + (t0) + seg * 8); \
    } \
} while (0)

    F_LOAD(0, 0);
    CP_COMMIT();

    for (int u = tid; u < 1152; u += 256)
        zs[u] = (qr0 + u < 2047) ? zoom[qr0 + u] : 0.f;
#pragma unroll
    for (int li = 0; li < 4; li++) {
        int idx = tid + li * 256;
        int row = idx >> 3, seg = idx & 7;
        *(uint4*)(sm + F_QH + row * 144 + seg * 16) = *(const uint4*)(gQh + row * HD + seg * 8);
        *(uint4*)(sm + F_QL + row * 144 + seg * 16) = *(const uint4*)(gQl + row * HD + seg * 8);
    }

    float accO[8][4];
#pragma unroll
    for (int nt = 0; nt < 8; nt++)
#pragma unroll
        for (int r = 0; r < 4; r++) accO[nt][r] = 0.f;
    float mi0 = -3.0e38f, mi1 = -3.0e38f, li0 = 0.f, li1 = 0.f;

    for (int kt = 0; kt < 8; kt++) {
        const int t0 = kt * 128;
        if (kt < 7) {
            F_LOAD((kt + 1) & 1, t0 + 128);
            CP_COMMIT();
            CP_WAIT(1);
        } else {
            CP_WAIT(0);
        }
        __syncthreads();

        char* sKh = sm + F_K(kt & 1);
        char* sKl = sKh + 18432;
        char* sVh = sm + F_V(kt & 1);
        char* sVl = sVh + 17408;

        float sc[16][4];
#pragma unroll
        for (int nt = 0; nt < 16; nt++)
#pragma unroll
            for (int r = 0; r < 4; r++) sc[nt][r] = 0.f;

#pragma unroll
        for (int ks = 0; ks < 4; ks++) {
            const uint32_t kb = ks * 32;
            uint32_t aoff = (wq + lr) * 144 + kb + lc * 4;
            uint32_t Ahf[4], Alf[4];
            Ahf[0] = *(const uint32_t*)(sm + F_QH + aoff);
            Ahf[1] = *(const uint32_t*)(sm + F_QH + aoff + 8 * 144);
            Ahf[2] = *(const uint32_t*)(sm + F_QH + aoff + 16);
            Ahf[3] = *(const uint32_t*)(sm + F_QH + aoff + 8 * 144 + 16);
            Alf[0] = *(const uint32_t*)(sm + F_QL + aoff);
            Alf[1] = *(const uint32_t*)(sm + F_QL + aoff + 8 * 144);
            Alf[2] = *(const uint32_t*)(sm + F_QL + aoff + 16);
            Alf[3] = *(const uint32_t*)(sm + F_QL + aoff + 8 * 144 + 16);
#pragma unroll
            for (int ng = 0; ng < 4; ng++) {
                uint32_t Bh[4][2], Bl[4][2];
#pragma unroll
                for (int t = 0; t < 4; t++) {
                    int nt = ng * 4 + t;
                    uint32_t boff = (nt * 8 + lr) * 144 + kb + lc * 4;
                    Bh[t][0] = *(const uint32_t*)(sKh + boff);
                    Bh[t][1] = *(const uint32_t*)(sKh + boff + 16);
                    Bl[t][0] = *(const uint32_t*)(sKl + boff);
                    Bl[t][1] = *(const uint32_t*)(sKl + boff + 16);
                }
#pragma unroll
                for (int t = 0; t < 4; t++)
                    mma16816(sc[ng * 4 + t], Ahf, Bh[t]);
#pragma unroll
                for (int t = 0; t < 4; t++)
                    mma16816(sc[ng * 4 + t], Ahf, Bl[t]);
#pragma unroll
                for (int t = 0; t < 4; t++)
                    mma16816(sc[ng * 4 + t], Alf, Bh[t]);
            }
        }

        const int row_l0 = wq + lr;
        float mx0 = -3.0e38f, mx1 = -3.0e38f;
#pragma unroll
        for (int nt = 0; nt < 16; nt++) {
            int keyg = t0 + nt * 8 + lc * 2;
            const float* bp = gB + (size_t)(qr0 + row_l0) * SS + keyg;
            float2 bv0 = __ldcs((const float2*)bp);
            float2 bv1 = __ldcs((const float2*)(bp + 8 * SS));
            int u0 = row_l0 - keyg + 1023;
            sc[nt][0] = fmaf(sc[nt][0], SCALE, bv0.x + zs[u0]);
            sc[nt][1] = fmaf(sc[nt][1], SCALE, bv0.y + zs[u0 - 1]);
            sc[nt][2] = fmaf(sc[nt][2], SCALE, bv1.x + zs[u0 + 8]);
            sc[nt][3] = fmaf(sc[nt][3], SCALE, bv1.y + zs[u0 + 7]);
            mx0 = fmaxf(mx0, fmaxf(sc[nt][0], sc[nt][1]));
            mx1 = fmaxf(mx1, fmaxf(sc[nt][2], sc[nt][3]));
        }
#pragma unroll
        for (int off = 1; off <= 2; off <<= 1) {
            mx0 = fmaxf(mx0, __shfl_xor_sync(0xffffffffu, mx0, off));
            mx1 = fmaxf(mx1, __shfl_xor_sync(0xffffffffu, mx1, off));
        }
        float m0n = fmaxf(mi0, mx0), m1n = fmaxf(mi1, mx1);
        float a0 = __expf(mi0 - m0n), a1 = __expf(mi1 - m1n);
        mi0 = m0n; mi1 = m1n;
        float rs0 = 0.f, rs1 = 0.f;
#pragma unroll
        for (int nt = 0; nt < 16; nt++) {
            sc[nt][0] = __expf(sc[nt][0] - m0n);
            sc[nt][1] = __expf(sc[nt][1] - m0n);
            sc[nt][2] = __expf(sc[nt][2] - m1n);
            sc[nt][3] = __expf(sc[nt][3] - m1n);
            rs0 += sc[nt][0] + sc[nt][1];
            rs1 += sc[nt][2] + sc[nt][3];
        }
#pragma unroll
        for (int off = 1; off <= 2; off <<= 1) {
            rs0 += __shfl_xor_sync(0xffffffffu, rs0, off);
            rs1 += __shfl_xor_sync(0xffffffffu, rs1, off);
        }
        li0 = li0 * a0 + rs0;
        li1 = li1 * a1 + rs1;
#pragma unroll
        for (int nt = 0; nt < 8; nt++) {
            accO[nt][0] *= a0; accO[nt][1] *= a0;
            accO[nt][2] *= a1; accO[nt][3] *= a1;
        }

#pragma unroll
        for (int g = 0; g < 8; g++) {
            uint32_t Ph[4], Pl[4];
#pragma unroll
            for (int t = 0; t < 2; t++)
#pragma unroll
                for (int r = 0; r < 2; r++) {
                    float x = sc[2 * g + t][2 * r], y = sc[2 * g + t][2 * r + 1];
                    __nv_bfloat162 hp = __floats2bfloat162_rn(x, y);
                    float2 hf = __bfloat1622float2(hp);
                    __nv_bfloat162 lp = __floats2bfloat162_rn(x - hf.x, y - hf.y);
                    Ph[t * 2 + r] = b2u(hp);
                    Pl[t * 2 + r] = b2u(lp);
                }
            const uint32_t kb = g * 32;
#pragma unroll
            for (int vg = 0; vg < 2; vg++) {
                uint32_t Vh[4][2], Vl[4][2];
#pragma unroll
                for (int t = 0; t < 4; t++) {
                    uint32_t boff = ((vg * 4 + t) * 8 + lr) * 272 + kb + lc * 4;
                    Vh[t][0] = *(const uint32_t*)(sVh + boff);
                    Vh[t][1] = *(const uint32_t*)(sVh + boff + 16);
                    Vl[t][0] = *(const uint32_t*)(sVl + boff);
                    Vl[t][1] = *(const uint32_t*)(sVl + boff + 16);
                }
#pragma unroll
                for (int t = 0; t < 4; t++)
                    mma16816(accO[vg * 4 + t], Ph, Vh[t]);
#pragma unroll
                for (int t = 0; t < 4; t++)
                    mma16816(accO[vg * 4 + t], Ph, Vl[t]);
#pragma unroll
                for (int t = 0; t < 4; t++)
                    mma16816(accO[vg * 4 + t], Pl, Vh[t]);
            }
        }
        __syncthreads();
    }

    float inv0 = 1.f / li0, inv1 = 1.f / li1;
    int row0 = qr0 + wq + lr;
#pragma unroll
    for (int nt = 0; nt < 8; nt++) {
        int col = h * HD + nt * 8 + lc * 2;
        *(float2*)(CtxF + ((size_t)(b * SS + row0)) * HIDDEN + col) =
            make_float2(accO[nt][0] * inv0, accO[nt][1] * inv0);
        *(float2*)(CtxF + ((size_t)(b * SS + row0 + 8)) * HIDDEN + col) =
            make_float2(accO[nt][2] * inv1, accO[nt][3] * inv1);
    }
}

extern "C" void kernel_launch(void* const* d_in, const int* in_sizes, int n_in,
                              void* d_out, int out_size)
{
    const float* q    = (const float*)d_in[0];
    const float* k    = (const float*)d_in[1];
    const float* v    = (const float*)d_in[2];
    const float* ab   = (const float*)d_in[3];
    const float* Wq   = (const float*)d_in[4];
    const float* bq   = (const float*)d_in[5];
    const float* Wk   = (const float*)d_in[6];
    const float* bk   = (const float*)d_in[7];
    const float* Wv   = (const float*)d_in[8];
    const float* bv   = (const float*)d_in[9];
    const float* Wo   = (const float*)d_in[10];
    const float* bo   = (const float*)d_in[11];
    const float* zoom = (const float*)d_in[12];

    int8_t *q0,*q1,*k0,*k1,*v0,*v1,*c0,*c1;
    int8_t *Wq0,*Wq1,*Wk0,*Wk1,*Wv0,*Wv1,*Wo0,*Wo1;
    float *sq,*sk,*sv,*sc_,*sWq,*sWk,*sWv,*sWo,*CtxF;
    __nv_bfloat16 *Qsh,*Qsl,*Ksh,*Ksl,*Vth,*Vtl;
    cudaGetSymbolAddress((void**)&q0, g_q0);   cudaGetSymbolAddress((void**)&q1, g_q1);
    cudaGetSymbolAddress((void**)&k0, g_k0);   cudaGetSymbolAddress((void**)&k1, g_k1);
    cudaGetSymbolAddress((void**)&v0, g_v0);   cudaGetSymbolAddress((void**)&v1, g_v1);
    cudaGetSymbolAddress((void**)&c0, g_c0);   cudaGetSymbolAddress((void**)&c1, g_c1);
    cudaGetSymbolAddress((void**)&Wq0, g_Wq0); cudaGetSymbolAddress((void**)&Wq1, g_Wq1);
    cudaGetSymbolAddress((void**)&Wk0, g_Wk0); cudaGetSymbolAddress((void**)&Wk1, g_Wk1);
    cudaGetSymbolAddress((void**)&Wv0, g_Wv0); cudaGetSymbolAddress((void**)&Wv1, g_Wv1);
    cudaGetSymbolAddress((void**)&Wo0, g_Wo0); cudaGetSymbolAddress((void**)&Wo1, g_Wo1);
    cudaGetSymbolAddress((void**)&sq, g_sq);   cudaGetSymbolAddress((void**)&sk, g_sk);
    cudaGetSymbolAddress((void**)&sv, g_sv);   cudaGetSymbolAddress((void**)&sc_, g_sc);
    cudaGetSymbolAddress((void**)&sWq, g_sWq); cudaGetSymbolAddress((void**)&sWk, g_sWk);
    cudaGetSymbolAddress((void**)&sWv, g_sWv); cudaGetSymbolAddress((void**)&sWo, g_sWo);
    cudaGetSymbolAddress((void**)&CtxF, g_CtxF);
    cudaGetSymbolAddress((void**)&Qsh, g_Qsh); cudaGetSymbolAddress((void**)&Qsl, g_Qsl);
    cudaGetSymbolAddress((void**)&Ksh, g_Ksh); cudaGetSymbolAddress((void**)&Ksl, g_Ksl);
    cudaGetSymbolAddress((void**)&Vth, g_Vth); cudaGetSymbolAddress((void**)&Vtl, g_Vtl);

    cudaFuncSetAttribute(gemm_s8_kernel,
                         cudaFuncAttributeMaxDynamicSharedMemorySize, QGEMM_SMEM);
    cudaFuncSetAttribute(flash_tc_kernel,
                         cudaFuncAttributeMaxDynamicSharedMemorySize, FLASH_SMEM);

    dim3 gg(HIDDEN / 128, (BB * SS) / 128);

    // ordered so the 6th launch (ncu -s 5 -c 1) is a GEMM
    quant_kernel<<<BB * SS, 256>>>(q, q0, q1, sq);
    quant_kernel<<<HIDDEN, 256>>>(Wq, Wq0, Wq1, sWq);
    quant_kernel<<<BB * SS, 256>>>(k, k0, k1, sk);
    quant_kernel<<<HIDDEN, 256>>>(Wk, Wk0, Wk1, sWk);
    quant_kernel<<<BB * SS, 256>>>(v, v0, v1, sv);
    gemm_s8_kernel<<<gg, 256, QGEMM_SMEM>>>(q0, q1, Wq0, Wq1, sq, sWq, bq,
                                            nullptr, Qsh, Qsl, 0);
    quant_kernel<<<HIDDEN, 256>>>(Wv, Wv0, Wv1, sWv);
    gemm_s8_kernel<<<gg, 256, QGEMM_SMEM>>>(k0, k1, Wk0, Wk1, sk, sWk, bk,
                                            nullptr, Ksh, Ksl, 0);
    quant_kernel<<<HIDDEN, 256>>>(Wo, Wo0, Wo1, sWo);
    gemm_s8_kernel<<<gg, 256, QGEMM_SMEM>>>(v0, v1, Wv0, Wv1, sv, sWv, bv,
                                            nullptr, Vth, Vtl, 2);

    dim3 gf(SS / 128, NH, BB);
    flash_tc_kernel<<<gf, 256, FLASH_SMEM>>>(Qsh, Qsl, Ksh, Ksl, Vth, Vtl, ab, zoom, CtxF);

    quant_kernel<<<BB * SS, 256>>>(CtxF, c0, c1, sc_);
    gemm_s8_kernel<<<gg, 256, QGEMM_SMEM>>>(c0, c1, Wo0, Wo1, sc_, sWo, bo,
                                            (float*)d_out, nullptr, nullptr, 1);
}

// round 17
// speedup vs baseline: 1.9497x; 1.9497x over previous
#include <cuda_runtime.h>
#include <cuda_bf16.h>
#include <cstdint>
#include <cstring>

#define HIDDEN 1024
#define BB 8
#define SS 1024
#define NH 16
#define HD 64
#define SCALE 0.125f

// ---------------------------------------------------------------------------
// Scratch (no cudaMalloc allowed). All bf16 split hi/lo pairs.
// ---------------------------------------------------------------------------
#define NELEM (BB * SS * HIDDEN)     // 8M
__device__ __nv_bfloat16 g_qh[NELEM], g_ql[NELEM];
__device__ __nv_bfloat16 g_kh[NELEM], g_kl[NELEM];
__device__ __nv_bfloat16 g_vh[NELEM], g_vl[NELEM];
__device__ __nv_bfloat16 g_Wqh[HIDDEN*HIDDEN], g_Wql[HIDDEN*HIDDEN];
__device__ __nv_bfloat16 g_Wkh[HIDDEN*HIDDEN], g_Wkl[HIDDEN*HIDDEN];
__device__ __nv_bfloat16 g_Wvh[HIDDEN*HIDDEN], g_Wvl[HIDDEN*HIDDEN];
__device__ __nv_bfloat16 g_Woh[HIDDEN*HIDDEN], g_Wol[HIDDEN*HIDDEN];
__device__ __nv_bfloat16 g_Qsh[NELEM], g_Qsl[NELEM];   // [b,h,s,d]
__device__ __nv_bfloat16 g_Ksh[NELEM], g_Ksl[NELEM];   // [b,h,s,d]
__device__ __nv_bfloat16 g_Vth[NELEM], g_Vtl[NELEM];   // [b,h,d,s]
__device__ __nv_bfloat16 g_Ch[NELEM],  g_Cl[NELEM];    // ctx [b,s,1024]

__device__ __forceinline__ uint32_t b2u(__nv_bfloat162 h) {
    uint32_t u; memcpy(&u, &h, 4); return u;
}

__device__ __forceinline__ void mma16816(float* c, const uint32_t* a, const uint32_t* b) {
    asm volatile(
        "mma.sync.aligned.m16n8k16.row.col.f32.bf16.bf16.f32 "
        "{%0,%1,%2,%3}, {%4,%5,%6,%7}, {%8,%9}, {%0,%1,%2,%3};"
        : "+f"(c[0]), "+f"(c[1]), "+f"(c[2]), "+f"(c[3])
        : "r"(a[0]), "r"(a[1]), "r"(a[2]), "r"(a[3]), "r"(b[0]), "r"(b[1]));
}

__device__ __forceinline__ void ldsm_x4(uint32_t* r, uint32_t addr) {
    asm volatile("ldmatrix.sync.aligned.m8n8.x4.shared.b16 {%0,%1,%2,%3}, [%4];"
                 : "=r"(r[0]), "=r"(r[1]), "=r"(r[2]), "=r"(r[3]) : "r"(addr));
}

__device__ __forceinline__ uint32_t smem_u32(const void* p) {
    uint32_t a;
    asm("{ .reg .u64 t; cvta.to.shared.u64 t, %1; cvt.u32.u64 %0, t; }" : "=r"(a) : "l"(p));
    return a;
}

#define CP_ASYNC16(dst, src) \
    asm volatile("cp.async.cg.shared.global [%0], [%1], 16;" :: "r"(dst), "l"(src))
#define CP_COMMIT() asm volatile("cp.async.commit_group;" ::: "memory")
#define CP_WAIT(n)  asm volatile("cp.async.wait_group %0;" :: "n"(n) : "memory")

__device__ __forceinline__ void split_store2(float x, float y,
                                             __nv_bfloat16* H, __nv_bfloat16* L, size_t off) {
    __nv_bfloat162 hp = __floats2bfloat162_rn(x, y);
    float2 hf = __bfloat1622float2(hp);
    __nv_bfloat162 lp = __floats2bfloat162_rn(x - hf.x, y - hf.y);
    *(uint32_t*)(H + off) = b2u(hp);
    *(uint32_t*)(L + off) = b2u(lp);
}

__device__ __forceinline__ void split_store1(float x, __nv_bfloat16* H, __nv_bfloat16* L, size_t off) {
    __nv_bfloat16 h = __float2bfloat16(x);
    H[off] = h;
    L[off] = __float2bfloat16(x - __bfloat162float(h));
}

// ---------------------------------------------------------------------------
// One-time fp32 -> bf16 hi/lo split
// ---------------------------------------------------------------------------
__global__ __launch_bounds__(256)
void split_kernel(const float* __restrict__ X, __nv_bfloat16* __restrict__ Xh,
                  __nv_bfloat16* __restrict__ Xl, int n4)
{
    int i = blockIdx.x * blockDim.x + threadIdx.x;
    if (i >= n4) return;
    float4 v = ((const float4*)X)[i];
    __nv_bfloat162 h01 = __floats2bfloat162_rn(v.x, v.y);
    __nv_bfloat162 h23 = __floats2bfloat162_rn(v.z, v.w);
    float2 f01 = __bfloat1622float2(h01);
    float2 f23 = __bfloat1622float2(h23);
    __nv_bfloat162 l01 = __floats2bfloat162_rn(v.x - f01.x, v.y - f01.y);
    __nv_bfloat162 l23 = __floats2bfloat162_rn(v.z - f23.x, v.w - f23.y);
    ((uint2*)Xh)[i] = make_uint2(b2u(h01), b2u(h23));
    ((uint2*)Xl)[i] = make_uint2(b2u(l01), b2u(l23));
}

// ---------------------------------------------------------------------------
// bf16 split GEMM, cp.async double-buffered, K-chunk 64, ldmatrix fragments.
// (= the 1192us config with ONLY the fragment loads changed to LDSM.x4;
//  lane mappings identical to the correctness-verified R7 kernel.)
// mode 0: split-bf16 out [b,h,s,d]; mode 1: fp32 row-major; mode 2: split Vt
// ---------------------------------------------------------------------------
#define G_STG 73728      // bytes per stage (4 buffers x 128 rows x 144B)
#define G_AL 18432
#define G_BH 36864
#define G_BL 55296
#define GEMM_SMEM (2 * G_STG)

__global__ __launch_bounds__(256)
void gemm_bf16_kernel(const __nv_bfloat16* __restrict__ Ah, const __nv_bfloat16* __restrict__ Al,
                      const __nv_bfloat16* __restrict__ Wh, const __nv_bfloat16* __restrict__ Wl,
                      const float* __restrict__ bias, float* __restrict__ outF,
                      __nv_bfloat16* __restrict__ Oh, __nv_bfloat16* __restrict__ Ol, int mode)
{
    extern __shared__ char dsm[];
    const uint32_t su = smem_u32(dsm);
    const int tid = threadIdx.x;
    const int wid = tid >> 5, lane = tid & 31;
    const int lr = lane >> 2, lc = lane & 3;
    const int n0 = blockIdx.x * 128, m0 = blockIdx.y * 128;
    const int wm = (wid >> 2) * 64;
    const int wn = (wid & 3) * 32;

    // ldmatrix lane address selectors (verified in R7)
    const int aRow = lane & 15;
    const int aK   = (lane >> 4) << 4;
    const int bRow = (lane & 7) + ((lane >> 4) << 3);
    const int bK   = ((lane >> 3) & 1) << 4;

    float acc[4][4][4];
#pragma unroll
    for (int i = 0; i < 4; i++)
#pragma unroll
        for (int j = 0; j < 4; j++)
#pragma unroll
            for (int r = 0; r < 4; r++) acc[i][j][r] = 0.f;

#define G_LOAD(s, kt) do { \
    uint32_t base = su + (s) * G_STG; \
    _Pragma("unroll") \
    for (int li = 0; li < 4; li++) { \
        int idx = tid + li * 256; \
        int row = idx >> 3, seg = idx & 7; \
        uint32_t d0 = base + row * 144 + seg * 16; \
        size_t go = (size_t)row * HIDDEN + (kt) * 64 + seg * 8; \
        CP_ASYNC16(d0,        Ah + (size_t)m0 * HIDDEN + go); \
        CP_ASYNC16(d0 + G_AL, Al + (size_t)m0 * HIDDEN + go); \
        CP_ASYNC16(d0 + G_BH, Wh + (size_t)n0 * HIDDEN + go); \
        CP_ASYNC16(d0 + G_BL, Wl + (size_t)n0 * HIDDEN + go); \
    } \
} while (0)

    G_LOAD(0, 0);
    CP_COMMIT();

    for (int kt = 0; kt < 16; kt++) {
        if (kt < 15) {
            G_LOAD((kt + 1) & 1, kt + 1);
            CP_COMMIT();
            CP_WAIT(1);
        } else {
            CP_WAIT(0);
        }
        __syncthreads();

        const uint32_t sA = su + (kt & 1) * G_STG;
        const uint32_t sB = sA + G_BH;

#pragma unroll
        for (int ks = 0; ks < 4; ks++) {
            const uint32_t kb = ks * 32;
            uint32_t Af[4][8];
#pragma unroll
            for (int i = 0; i < 4; i++) {
                uint32_t addr = sA + (wm + i * 16 + aRow) * 144 + kb + aK;
                ldsm_x4(&Af[i][0], addr);
                ldsm_x4(&Af[i][4], addr + G_AL);
            }
#pragma unroll
            for (int jp = 0; jp < 2; jp++) {
                uint32_t Bh4[4], Bl4[4];
                uint32_t baddr = sB + (wn + jp * 16 + bRow) * 144 + kb + bK;
                ldsm_x4(Bh4, baddr);
                ldsm_x4(Bl4, baddr + (G_BL - G_BH));
#pragma unroll
                for (int i = 0; i < 4; i++) {
#pragma unroll
                    for (int t = 0; t < 2; t++) {
                        int jn = jp * 2 + t;
                        mma16816(acc[i][jn], &Af[i][0], &Bh4[t * 2]);
                        mma16816(acc[i][jn], &Af[i][0], &Bl4[t * 2]);
                        mma16816(acc[i][jn], &Af[i][4], &Bh4[t * 2]);
                    }
                }
            }
        }
        __syncthreads();
    }

#pragma unroll
    for (int i = 0; i < 4; i++) {
#pragma unroll
        for (int jn = 0; jn < 4; jn++) {
            int row = m0 + wm + i * 16 + lr;
            int row8 = row + 8;
            int col = n0 + wn + jn * 8 + lc * 2;
            float x0 = acc[i][jn][0] + bias[col], y0 = acc[i][jn][1] + bias[col + 1];
            float x1 = acc[i][jn][2] + bias[col], y1 = acc[i][jn][3] + bias[col + 1];
            if (mode == 0) {
                int b0_ = row >> 10, s0_ = row & 1023;
                int b1_ = row8 >> 10, s1_ = row8 & 1023;
                int h = col >> 6, d = col & 63;
                split_store2(x0, y0, Oh, Ol, (((size_t)(b0_ * NH + h)) * SS + s0_) * HD + d);
                split_store2(x1, y1, Oh, Ol, (((size_t)(b1_ * NH + h)) * SS + s1_) * HD + d);
            } else if (mode == 1) {
                *(float2*)(outF + (size_t)row * HIDDEN + col) = make_float2(x0, y0);
                *(float2*)(outF + (size_t)row8 * HIDDEN + col) = make_float2(x1, y1);
            } else {
                int b0_ = row >> 10, s0_ = row & 1023;
                int s1_ = row8 & 1023;
                int h = col >> 6, d = col & 63;
                size_t base = (size_t)(b0_ * NH + h) * HD;
                split_store1(x0, Oh, Ol, (base + d) * SS + s0_);
                split_store1(y0, Oh, Ol, (base + d + 1) * SS + s0_);
                split_store1(x1, Oh, Ol, (base + d) * SS + s1_);
                split_store1(y1, Oh, Ol, (base + d + 1) * SS + s1_);
            }
        }
    }
}

// ---------------------------------------------------------------------------
// Tensor-core flash attention, pre-split bf16 inputs, cp.async pipelined K/V,
// ldmatrix fragments (verified in R7). 1 CTA per (b, h, 128 q rows).
// ---------------------------------------------------------------------------
#define F_QH 0
#define F_QL 18432
#define F_K(s) (36864 + (s) * 36864)    // KL at +18432
#define F_V(s) (110592 + (s) * 34816)   // VL at +17408
#define F_ZS 180224
#define FLASH_SMEM (F_ZS + 1152 * 4)

__global__ __launch_bounds__(256)
void flash_tc_kernel(const __nv_bfloat16* __restrict__ Qhg, const __nv_bfloat16* __restrict__ Qlg,
                     const __nv_bfloat16* __restrict__ Khg, const __nv_bfloat16* __restrict__ Klg,
                     const __nv_bfloat16* __restrict__ Vthg, const __nv_bfloat16* __restrict__ Vtlg,
                     const float* __restrict__ attn_bias, const float* __restrict__ zoom,
                     __nv_bfloat16* __restrict__ Ch, __nv_bfloat16* __restrict__ Cl)
{
    extern __shared__ char sm[];
    const uint32_t su = smem_u32(sm);
    float* zs = (float*)(sm + F_ZS);

    const int tid = threadIdx.x;
    const int wid = tid >> 5, lane = tid & 31;
    const int lr = lane >> 2, lc = lane & 3;
    const int wq = wid * 16;
    const int qt = blockIdx.x, h = blockIdx.y, b = blockIdx.z;
    const int qr0 = qt * 128;

    const int aRow = lane & 15;
    const int aK   = (lane >> 4) << 4;
    const int bRow = (lane & 7) + ((lane >> 4) << 3);
    const int bK   = ((lane >> 3) & 1) << 4;

    const __nv_bfloat16* gQh  = Qhg + (((size_t)(b * NH + h)) * SS + qr0) * HD;
    const __nv_bfloat16* gQl  = Qlg + (((size_t)(b * NH + h)) * SS + qr0) * HD;
    const __nv_bfloat16* gKh  = Khg + ((size_t)(b * NH + h)) * SS * HD;
    const __nv_bfloat16* gKl  = Klg + ((size_t)(b * NH + h)) * SS * HD;
    const __nv_bfloat16* gVth = Vthg + ((size_t)(b * NH + h)) * HD * SS;
    const __nv_bfloat16* gVtl = Vtlg + ((size_t)(b * NH + h)) * HD * SS;
    const float* gB = attn_bias + (size_t)b * SS * SS;

#define F_LOAD(s, t0) do { \
    _Pragma("unroll") \
    for (int li = 0; li < 4; li++) { \
        int idx = tid + li * 256; \
        int row = idx >> 3, seg = idx & 7; \
        uint32_t dk = su + F_K(s) + row * 144 + seg * 16; \
        CP_ASYNC16(dk,         gKh + (size_t)((t0) + row) * HD + seg * 8); \
        CP_ASYNC16(dk + 18432, gKl + (size_t)((t0) + row) * HD + seg * 8); \
    } \
    _Pragma("unroll") \
    for (int li = 0; li < 4; li++) { \
        int idx = tid + li * 256; \
        int d = idx >> 4, seg = idx & 15; \
        uint32_t dv = su + F_V(s) + d * 272 + seg * 16; \
        CP_ASYNC16(dv,         gVth + (size_t)d * SS + (t0) + seg * 8); \
        CP_ASYNC16(dv + 17408, gVtl + (size_t)d * SS + (t0) + seg * 8); \
    } \
} while (0)

    F_LOAD(0, 0);
    CP_COMMIT();

    for (int u = tid; u < 1152; u += 256)
        zs[u] = (qr0 + u < 2047) ? zoom[qr0 + u] : 0.f;
#pragma unroll
    for (int li = 0; li < 4; li++) {
        int idx = tid + li * 256;
        int row = idx >> 3, seg = idx & 7;
        *(uint4*)(sm + F_QH + row * 144 + seg * 16) = *(const uint4*)(gQh + row * HD + seg * 8);
        *(uint4*)(sm + F_QL + row * 144 + seg * 16) = *(const uint4*)(gQl + row * HD + seg * 8);
    }

    float accO[8][4];
#pragma unroll
    for (int nt = 0; nt < 8; nt++)
#pragma unroll
        for (int r = 0; r < 4; r++) accO[nt][r] = 0.f;
    float mi0 = -3.0e38f, mi1 = -3.0e38f, li0 = 0.f, li1 = 0.f;

    for (int kt = 0; kt < 8; kt++) {
        const int t0 = kt * 128;
        if (kt < 7) {
            F_LOAD((kt + 1) & 1, t0 + 128);
            CP_COMMIT();
            CP_WAIT(1);
        } else {
            CP_WAIT(0);
        }
        __syncthreads();

        const uint32_t sK = su + F_K(kt & 1);
        const uint32_t sV = su + F_V(kt & 1);

        // S = Q.K^T : warp computes 16 x 128
        float sc[16][4];
#pragma unroll
        for (int nt = 0; nt < 16; nt++)
#pragma unroll
            for (int r = 0; r < 4; r++) sc[nt][r] = 0.f;

#pragma unroll
        for (int ks = 0; ks < 4; ks++) {
            const uint32_t kb = ks * 32;
            uint32_t Qh4[4], Ql4[4];
            uint32_t qaddr = su + F_QH + (wq + aRow) * 144 + kb + aK;
            ldsm_x4(Qh4, qaddr);
            ldsm_x4(Ql4, qaddr + F_QL);
#pragma unroll
            for (int tp = 0; tp < 8; tp++) {
                uint32_t Kh4[4], Kl4[4];
                uint32_t kaddr = sK + (tp * 16 + bRow) * 144 + kb + bK;
                ldsm_x4(Kh4, kaddr);
                ldsm_x4(Kl4, kaddr + 18432);
#pragma unroll
                for (int t = 0; t < 2; t++) {
                    int nt = tp * 2 + t;
                    mma16816(sc[nt], Qh4, &Kh4[t * 2]);
                    mma16816(sc[nt], Qh4, &Kl4[t * 2]);
                    mma16816(sc[nt], Ql4, &Kh4[t * 2]);
                }
            }
        }

        // scale + biases, online softmax
        const int row_l0 = wq + lr;
        float mx0 = -3.0e38f, mx1 = -3.0e38f;
#pragma unroll
        for (int nt = 0; nt < 16; nt++) {
            int keyg = t0 + nt * 8 + lc * 2;
            const float* bp = gB + (size_t)(qr0 + row_l0) * SS + keyg;
            float2 bv0 = __ldcs((const float2*)bp);
            float2 bv1 = __ldcs((const float2*)(bp + 8 * SS));
            int u0 = row_l0 - keyg + 1023;
            sc[nt][0] = fmaf(sc[nt][0], SCALE, bv0.x + zs[u0]);
            sc[nt][1] = fmaf(sc[nt][1], SCALE, bv0.y + zs[u0 - 1]);
            sc[nt][2] = fmaf(sc[nt][2], SCALE, bv1.x + zs[u0 + 8]);
            sc[nt][3] = fmaf(sc[nt][3], SCALE, bv1.y + zs[u0 + 7]);
            mx0 = fmaxf(mx0, fmaxf(sc[nt][0], sc[nt][1]));
            mx1 = fmaxf(mx1, fmaxf(sc[nt][2], sc[nt][3]));
        }
#pragma unroll
        for (int off = 1; off <= 2; off <<= 1) {
            mx0 = fmaxf(mx0, __shfl_xor_sync(0xffffffffu, mx0, off));
            mx1 = fmaxf(mx1, __shfl_xor_sync(0xffffffffu, mx1, off));
        }
        float m0n = fmaxf(mi0, mx0), m1n = fmaxf(mi1, mx1);
        float a0 = __expf(mi0 - m0n), a1 = __expf(mi1 - m1n);
        mi0 = m0n; mi1 = m1n;
        float rs0 = 0.f, rs1 = 0.f;
#pragma unroll
        for (int nt = 0; nt < 16; nt++) {
            sc[nt][0] = __expf(sc[nt][0] - m0n);
            sc[nt][1] = __expf(sc[nt][1] - m0n);
            sc[nt][2] = __expf(sc[nt][2] - m1n);
            sc[nt][3] = __expf(sc[nt][3] - m1n);
            rs0 += sc[nt][0] + sc[nt][1];
            rs1 += sc[nt][2] + sc[nt][3];
        }
#pragma unroll
        for (int off = 1; off <= 2; off <<= 1) {
            rs0 += __shfl_xor_sync(0xffffffffu, rs0, off);
            rs1 += __shfl_xor_sync(0xffffffffu, rs1, off);
        }
        li0 = li0 * a0 + rs0;
        li1 = li1 * a1 + rs1;
#pragma unroll
        for (int nt = 0; nt < 8; nt++) {
            accO[nt][0] *= a0; accO[nt][1] *= a0;
            accO[nt][2] *= a1; accO[nt][3] *= a1;
        }

        // O += P.V  (P in registers; hi/lo split of P)
#pragma unroll
        for (int g = 0; g < 8; g++) {
            uint32_t Ph[4], Pl[4];
#pragma unroll
            for (int t = 0; t < 2; t++)
#pragma unroll
                for (int r = 0; r < 2; r++) {
                    float x = sc[2 * g + t][2 * r], y = sc[2 * g + t][2 * r + 1];
                    __nv_bfloat162 hp = __floats2bfloat162_rn(x, y);
                    float2 hf = __bfloat1622float2(hp);
                    __nv_bfloat162 lp = __floats2bfloat162_rn(x - hf.x, y - hf.y);
                    Ph[t * 2 + r] = b2u(hp);
                    Pl[t * 2 + r] = b2u(lp);
                }
            const uint32_t kbv = g * 32;
#pragma unroll
            for (int vp = 0; vp < 4; vp++) {
                uint32_t Vh4[4], Vl4[4];
                uint32_t vaddr = sV + (vp * 16 + bRow) * 272 + kbv + bK;
                ldsm_x4(Vh4, vaddr);
                ldsm_x4(Vl4, vaddr + 17408);
#pragma unroll
                for (int t = 0; t < 2; t++) {
                    int nt = vp * 2 + t;
                    mma16816(accO[nt], Ph, &Vh4[t * 2]);
                    mma16816(accO[nt], Ph, &Vl4[t * 2]);
                    mma16816(accO[nt], Pl, &Vh4[t * 2]);
                }
            }
        }
        __syncthreads();
    }

    // epilogue: normalize, write split-bf16 Ctx[b][row][h*64+d]
    float inv0 = 1.f / li0, inv1 = 1.f / li1;
    int row0 = qr0 + wq + lr;
#pragma unroll
    for (int nt = 0; nt < 8; nt++) {
        int col = h * HD + nt * 8 + lc * 2;
        split_store2(accO[nt][0] * inv0, accO[nt][1] * inv0, Ch, Cl,
                     ((size_t)(b * SS + row0)) * HIDDEN + col);
        split_store2(accO[nt][2] * inv1, accO[nt][3] * inv1, Ch, Cl,
                     ((size_t)(b * SS + row0 + 8)) * HIDDEN + col);
    }
}

extern "C" void kernel_launch(void* const* d_in, const int* in_sizes, int n_in,
                              void* d_out, int out_size)
{
    const float* q    = (const float*)d_in[0];
    const float* k    = (const float*)d_in[1];
    const float* v    = (const float*)d_in[2];
    const float* ab   = (const float*)d_in[3];
    const float* Wq   = (const float*)d_in[4];
    const float* bq   = (const float*)d_in[5];
    const float* Wk   = (const float*)d_in[6];
    const float* bk   = (const float*)d_in[7];
    const float* Wv   = (const float*)d_in[8];
    const float* bv   = (const float*)d_in[9];
    const float* Wo   = (const float*)d_in[10];
    const float* bo   = (const float*)d_in[11];
    const float* zoom = (const float*)d_in[12];

    __nv_bfloat16 *qh, *ql, *kh, *kl, *vh, *vl;
    __nv_bfloat16 *Wqh, *Wql, *Wkh, *Wkl, *Wvh, *Wvl, *Woh, *Wol;
    __nv_bfloat16 *Qsh, *Qsl, *Ksh, *Ksl, *Vth, *Vtl, *Ch, *Cl;
    cudaGetSymbolAddress((void**)&qh, g_qh);   cudaGetSymbolAddress((void**)&ql, g_ql);
    cudaGetSymbolAddress((void**)&kh, g_kh);   cudaGetSymbolAddress((void**)&kl, g_kl);
    cudaGetSymbolAddress((void**)&vh, g_vh);   cudaGetSymbolAddress((void**)&vl, g_vl);
    cudaGetSymbolAddress((void**)&Wqh, g_Wqh); cudaGetSymbolAddress((void**)&Wql, g_Wql);
    cudaGetSymbolAddress((void**)&Wkh, g_Wkh); cudaGetSymbolAddress((void**)&Wkl, g_Wkl);
    cudaGetSymbolAddress((void**)&Wvh, g_Wvh); cudaGetSymbolAddress((void**)&Wvl, g_Wvl);
    cudaGetSymbolAddress((void**)&Woh, g_Woh); cudaGetSymbolAddress((void**)&Wol, g_Wol);
    cudaGetSymbolAddress((void**)&Qsh, g_Qsh); cudaGetSymbolAddress((void**)&Qsl, g_Qsl);
    cudaGetSymbolAddress((void**)&Ksh, g_Ksh); cudaGetSymbolAddress((void**)&Ksl, g_Ksl);
    cudaGetSymbolAddress((void**)&Vth, g_Vth); cudaGetSymbolAddress((void**)&Vtl, g_Vtl);
    cudaGetSymbolAddress((void**)&Ch, g_Ch);   cudaGetSymbolAddress((void**)&Cl, g_Cl);

    cudaFuncSetAttribute(gemm_bf16_kernel,
                         cudaFuncAttributeMaxDynamicSharedMemorySize, GEMM_SMEM);
    cudaFuncSetAttribute(flash_tc_kernel,
                         cudaFuncAttributeMaxDynamicSharedMemorySize, FLASH_SMEM);

    // one-time splits
    split_kernel<<<NELEM / 1024, 256>>>(q, qh, ql, NELEM / 4);
    split_kernel<<<NELEM / 1024, 256>>>(k, kh, kl, NELEM / 4);
    split_kernel<<<NELEM / 1024, 256>>>(v, vh, vl, NELEM / 4);
    split_kernel<<<HIDDEN * HIDDEN / 1024, 256>>>(Wq, Wqh, Wql, HIDDEN * HIDDEN / 4);
    split_kernel<<<HIDDEN * HIDDEN / 1024, 256>>>(Wk, Wkh, Wkl, HIDDEN * HIDDEN / 4);
    split_kernel<<<HIDDEN * HIDDEN / 1024, 256>>>(Wv, Wvh, Wvl, HIDDEN * HIDDEN / 4);
    split_kernel<<<HIDDEN * HIDDEN / 1024, 256>>>(Wo, Woh, Wol, HIDDEN * HIDDEN / 4);

    dim3 gg(HIDDEN / 128, (BB * SS) / 128);
    gemm_bf16_kernel<<<gg, 256, GEMM_SMEM>>>(qh, ql, Wqh, Wql, bq, nullptr, Qsh, Qsl, 0);
    gemm_bf16_kernel<<<gg, 256, GEMM_SMEM>>>(kh, kl, Wkh, Wkl, bk, nullptr, Ksh, Ksl, 0);
    gemm_bf16_kernel<<<gg, 256, GEMM_SMEM>>>(vh, vl, Wvh, Wvl, bv, nullptr, Vth, Vtl, 2);

    dim3 gf(SS / 128, NH, BB);
    flash_tc_kernel<<<gf, 256, FLASH_SMEM>>>(Qsh, Qsl, Ksh, Ksl, Vth, Vtl, ab, zoom, Ch, Cl);

    gemm_bf16_kernel<<<gg, 256, GEMM_SMEM>>>(Ch, Cl, Woh, Wol, bo, (float*)d_out,
                                             nullptr, nullptr, 1);
}